// round 15
// baseline (speedup 1.0000x reference)
#include <cuda_runtime.h>
#include <math.h>

// Problem constants: B=4, C=64, O=64, H=W=128, K=9 taps
// Scratch (device globals are allowed; no runtime allocation)
__device__ float g_xT [4 * 16384 * 64];   // x transposed to [b][h][w][c]  (16.8 MB)
__device__ float g_off[4 * 16384 * 18];   // offsets [b][h][w][18]         (4.7 MB)
__device__ float g_wT [9 * 64 * 64];      // dc_w rearranged [k][c][o]
__device__ float g_w18[10368];            // off_w rearranged [kk][c4][oc][4]
__device__ float g_y  [4 * 64 * 16384];   // pre-BN conv output, NCHW      (16.8 MB)
__device__ float g_ss [128];              // per-channel scale / shift

__device__ __forceinline__ void fma4(float4& a, float w, const float4 v) {
    a.x = fmaf(w, v.x, a.x);
    a.y = fmaf(w, v.y, a.y);
    a.z = fmaf(w, v.z, a.z);
    a.w = fmaf(w, v.w, a.w);
}

// ---------------------------------------------------------------------------
// K0a: rearrange weights.
//   g_wT[(k*64+c)*64+o]                = dc_w[(o*64+c)*9+k]
//   g_w18[((kk*16+c4)*18+oc)*4+comp]   = off_w[(oc*64+c4*4+comp)*9+kk]
// ---------------------------------------------------------------------------
__global__ void k_prep(const float* __restrict__ off_w, const float* __restrict__ dc_w) {
    int idx = blockIdx.x * 256 + threadIdx.x;
    if (idx < 36864) {
        int o = idx & 63, c = (idx >> 6) & 63, k = idx >> 12;
        g_wT[idx] = dc_w[(o * 64 + c) * 9 + k];
    }
    int j = idx - 36864;
    if (j >= 0 && j < 10368) {
        int comp = j & 3;
        int t    = j >> 2;
        int oc   = t % 18;
        int r    = t / 18;
        int c4   = r & 15;
        int kk   = r >> 4;
        g_w18[j] = off_w[(oc * 64 + c4 * 4 + comp) * 9 + kk];
    }
}

// ---------------------------------------------------------------------------
// K0b: transpose x NCHW -> NHWC (g_xT[b][hw][c])
// ---------------------------------------------------------------------------
__global__ void k_transpose(const float* __restrict__ x) {
    __shared__ float tile[32][33];
    int hw0 = blockIdx.x << 5;
    int c0  = blockIdx.y << 5;
    int b   = blockIdx.z;
    int tx  = threadIdx.x, ty = threadIdx.y;
#pragma unroll
    for (int i = 0; i < 4; ++i) {
        int c = c0 + ty + i * 8;
        tile[ty + i * 8][tx] = x[(((size_t)b * 64 + c) << 14) + hw0 + tx];
    }
    __syncthreads();
#pragma unroll
    for (int i = 0; i < 4; ++i) {
        int hw = hw0 + ty + i * 8;
        g_xT[(((size_t)b << 14) + hw) * 64 + c0 + tx] = tile[tx][ty + i * 8];
    }
}

// ---------------------------------------------------------------------------
// K1: offset conv (3x3, C=64 -> 18), zero padding.
// One thread per pixel; weights in smem (warp-broadcast reads).
// ---------------------------------------------------------------------------
__global__ void __launch_bounds__(256) k_offconv(const float* __restrict__ off_b) {
    __shared__ float4 ws[2592];                 // [kk][c4][oc] as float4 over comp
    int tid = threadIdx.x;
    const float4* wsrc = (const float4*)g_w18;
    for (int i = tid; i < 2592; i += 256) ws[i] = wsrc[i];
    __syncthreads();

    int pidx = (blockIdx.x << 8) + tid;         // 0 .. 65535
    int b = pidx >> 14, hw = pidx & 16383;
    int h = hw >> 7, w = hw & 127;

    float acc[18];
#pragma unroll
    for (int oc = 0; oc < 18; ++oc) acc[oc] = __ldg(off_b + oc);

    const float* xb = g_xT + ((size_t)b << 20);
#pragma unroll
    for (int kk = 0; kk < 9; ++kk) {
        int hy = h + kk / 3 - 1;
        int wx = w + (kk - (kk / 3) * 3) - 1;
        if ((unsigned)hy < 128u && (unsigned)wx < 128u) {
            const float4* src = (const float4*)(xb + (((hy << 7) + wx) << 6));
            const float4* wp  = ws + kk * 288;
#pragma unroll 4
            for (int c4 = 0; c4 < 16; ++c4) {
                float4 xv = src[c4];
                const float4* wq = wp + c4 * 18;
#pragma unroll
                for (int oc = 0; oc < 18; ++oc) {
                    float4 wv = wq[oc];
                    float t0 = fmaf(wv.x, xv.x, acc[oc]);
                    t0 = fmaf(wv.y, xv.y, t0);
                    t0 = fmaf(wv.z, xv.z, t0);
                    acc[oc] = fmaf(wv.w, xv.w, t0);
                }
            }
        }
    }
    float2* outp = (float2*)(g_off + (size_t)pidx * 18);
#pragma unroll
    for (int j2 = 0; j2 < 9; ++j2) outp[j2] = make_float2(acc[2 * j2], acc[2 * j2 + 1]);
}

// ---------------------------------------------------------------------------
// K2: deformable conv. Block = one batch b, one row h, half-row of 64 pixels.
// For each of 9 taps: bilinear-gather the 64x64 sampled slice into smem,
// then accumulate the 64(o) x 64(p) GEMM slice (thread tile 4x4).
// ---------------------------------------------------------------------------
__global__ void __launch_bounds__(256) k_deform(const float* __restrict__ dc_b) {
    __shared__ float offs[1152];        // [p][18]
    __shared__ float sK[64][68];        // [c][p] (+pad)
    __shared__ float Wk[4096];          // [c][o]

    int tid = threadIdx.x;
    int b  = blockIdx.x >> 8;
    int t  = blockIdx.x & 255;
    int h  = t >> 1;
    int w0 = (t & 1) << 6;
    int pix0 = (b << 14) + (h << 7) + w0;

    {
        const float4* src = (const float4*)(g_off + (size_t)pix0 * 18);
        float4* dst = (float4*)offs;
        for (int i = tid; i < 288; i += 256) dst[i] = src[i];
    }
    const float* xb = g_xT + ((size_t)b << 20);

    int q = tid >> 6, p = tid & 63;     // build mapping: channels [16q,16q+16), pixel p
    int ty = tid >> 4, tx = tid & 15;   // GEMM mapping: o tile ty*4, p tile tx*4

    float4 acc0 = make_float4(0.f, 0.f, 0.f, 0.f);
    float4 acc1 = acc0, acc2 = acc0, acc3 = acc0;

    __syncthreads();

#pragma unroll 1
    for (int k = 0; k < 9; ++k) {
        // prefetch this tap's weight slice into registers (stores after barrier)
        const float4* wsrc = (const float4*)(g_wT + (k << 12));
        float4 wv0 = wsrc[tid], wv1 = wsrc[tid + 256],
               wv2 = wsrc[tid + 512], wv3 = wsrc[tid + 768];

        // bilinear sample of 16 channels for pixel p at tap k
        int ky = k / 3;
        int kx = k - ky * 3;
        float dy = offs[p * 18 + 2 * k];
        float dx = offs[p * 18 + 2 * k + 1];
        float py = (float)(h + ky - 1) + dy;
        float px = (float)(w0 + p + kx - 1) + dx;
        float fy = floorf(py), fx = floorf(px);
        int y0 = (int)fy, x0 = (int)fx;
        float ay = py - fy, ax = px - fx;

        float4 a0 = make_float4(0.f, 0.f, 0.f, 0.f);
        float4 a1 = a0, a2 = a0, a3 = a0;
#pragma unroll
        for (int cn = 0; cn < 4; ++cn) {
            int yi = y0 + (cn >> 1);
            int xi = x0 + (cn & 1);
            float wy = (cn >> 1) ? ay : (1.0f - ay);
            float wxx = (cn & 1) ? ax : (1.0f - ax);
            float wgt = wy * wxx;
            if ((unsigned)yi < 128u && (unsigned)xi < 128u) {
                const float4* src =
                    (const float4*)(xb + ((((yi << 7) + xi) << 6) + (q << 4)));
                float4 v;
                v = src[0]; fma4(a0, wgt, v);
                v = src[1]; fma4(a1, wgt, v);
                v = src[2]; fma4(a2, wgt, v);
                v = src[3]; fma4(a3, wgt, v);
            }
        }

        __syncthreads();   // previous GEMM finished reading sK/Wk

        ((float4*)Wk)[tid]       = wv0;
        ((float4*)Wk)[tid + 256] = wv1;
        ((float4*)Wk)[tid + 512] = wv2;
        ((float4*)Wk)[tid + 768] = wv3;

        int cb = q << 4;
        sK[cb +  0][p] = a0.x; sK[cb +  1][p] = a0.y; sK[cb +  2][p] = a0.z; sK[cb +  3][p] = a0.w;
        sK[cb +  4][p] = a1.x; sK[cb +  5][p] = a1.y; sK[cb +  6][p] = a1.z; sK[cb +  7][p] = a1.w;
        sK[cb +  8][p] = a2.x; sK[cb +  9][p] = a2.y; sK[cb + 10][p] = a2.z; sK[cb + 11][p] = a2.w;
        sK[cb + 12][p] = a3.x; sK[cb + 13][p] = a3.y; sK[cb + 14][p] = a3.z; sK[cb + 15][p] = a3.w;

        __syncthreads();

#pragma unroll 8
        for (int c = 0; c < 64; ++c) {
            float4 aw = *(const float4*)&Wk[(c << 6) + (ty << 2)];
            float4 sv = *(const float4*)&sK[c][tx << 2];
            fma4(acc0, aw.x, sv);
            fma4(acc1, aw.y, sv);
            fma4(acc2, aw.z, sv);
            fma4(acc3, aw.w, sv);
        }
    }

    float4 bias = *(const float4*)(dc_b + (ty << 2));
    acc0.x += bias.x; acc0.y += bias.x; acc0.z += bias.x; acc0.w += bias.x;
    acc1.x += bias.y; acc1.y += bias.y; acc1.z += bias.y; acc1.w += bias.y;
    acc2.x += bias.z; acc2.y += bias.z; acc2.z += bias.z; acc2.w += bias.z;
    acc3.x += bias.w; acc3.y += bias.w; acc3.z += bias.w; acc3.w += bias.w;

    int o0 = ty << 2;
    float* ybase = g_y + (((size_t)((b << 6) + o0)) << 14) + (h << 7) + w0 + (tx << 2);
    *(float4*)(ybase)         = acc0;
    *(float4*)(ybase + 16384) = acc1;
    *(float4*)(ybase + 32768) = acc2;
    *(float4*)(ybase + 49152) = acc3;
}

// ---------------------------------------------------------------------------
// K3: per-channel BN stats over (B,H,W); writes scale/shift.
// ---------------------------------------------------------------------------
__global__ void k_stats(const float* __restrict__ gamma, const float* __restrict__ beta) {
    int o = blockIdx.x, tid = threadIdx.x;
    float s = 0.f, s2 = 0.f;
#pragma unroll
    for (int bb = 0; bb < 4; ++bb) {
        const float4* base = (const float4*)(g_y + (((size_t)((bb << 6) + o)) << 14));
        for (int j = tid; j < 4096; j += 256) {
            float4 v = base[j];
            s += v.x + v.y + v.z + v.w;
            s2 = fmaf(v.x, v.x, s2);
            s2 = fmaf(v.y, v.y, s2);
            s2 = fmaf(v.z, v.z, s2);
            s2 = fmaf(v.w, v.w, s2);
        }
    }
#pragma unroll
    for (int off = 16; off > 0; off >>= 1) {
        s  += __shfl_down_sync(0xffffffffu, s,  off);
        s2 += __shfl_down_sync(0xffffffffu, s2, off);
    }
    __shared__ float rs[8], rs2[8];
    if ((tid & 31) == 0) { rs[tid >> 5] = s; rs2[tid >> 5] = s2; }
    __syncthreads();
    if (tid == 0) {
        float S = 0.f, S2 = 0.f;
#pragma unroll
        for (int i = 0; i < 8; ++i) { S += rs[i]; S2 += rs2[i]; }
        const float inv = 1.0f / 65536.0f;
        float mu   = S * inv;
        float var  = fmaf(S2, inv, -mu * mu);
        float rstd = rsqrtf(var + 1e-5f);
        float sc   = rstd * gamma[o];
        g_ss[o]      = sc;
        g_ss[64 + o] = beta[o] - mu * sc;
    }
}

// ---------------------------------------------------------------------------
// K4: normalize + relu, write final output (NCHW)
// ---------------------------------------------------------------------------
__global__ void k_norm(float* __restrict__ out) {
    int gi = (blockIdx.x << 8) + threadIdx.x;   // float4 index, 1,048,576 total
    int o  = (gi >> 12) & 63;
    float sc = g_ss[o], sh = g_ss[64 + o];
    float4 v = ((const float4*)g_y)[gi];
    float4 r;
    r.x = fmaxf(fmaf(v.x, sc, sh), 0.f);
    r.y = fmaxf(fmaf(v.y, sc, sh), 0.f);
    r.z = fmaxf(fmaf(v.z, sc, sh), 0.f);
    r.w = fmaxf(fmaf(v.w, sc, sh), 0.f);
    ((float4*)out)[gi] = r;
}

// ---------------------------------------------------------------------------
extern "C" void kernel_launch(void* const* d_in, const int* in_sizes, int n_in,
                              void* d_out, int out_size) {
    const float* x     = (const float*)d_in[0];
    const float* off_w = (const float*)d_in[1];
    const float* off_b = (const float*)d_in[2];
    const float* dc_w  = (const float*)d_in[3];
    const float* dc_b  = (const float*)d_in[4];
    const float* gamma = (const float*)d_in[5];
    const float* beta  = (const float*)d_in[6];
    float* out = (float*)d_out;

    k_prep<<<185, 256>>>(off_w, dc_w);

    dim3 tb(32, 8), tg(512, 2, 4);
    k_transpose<<<tg, tb>>>(x);

    k_offconv<<<256, 256>>>(off_b);     // 65536 pixels / 256
    k_deform <<<1024, 256>>>(dc_b);     // 65536 pixels / 64
    k_stats  <<<64, 256>>>(gamma, beta);
    k_norm   <<<4096, 256>>>(out);
}